// round 6
// baseline (speedup 1.0000x reference)
#include <cuda_runtime.h>
#include <cuda_bf16.h>
#include <cstdint>
#include <math.h>

#define DIM   192
#define HEADS 6
#define HD    32
#define RLOW  128
#define NSEQ  3136
#define BATCH 32
#define MTOT  (BATCH * NSEQ)   // 100352

// ================= scratch (device globals) =================
__device__ __align__(256) __nv_bfloat16 g_xh[MTOT * DIM], g_xl[MTOT * DIM];
__device__ __align__(256) __nv_bfloat16 g_qh[MTOT * DIM];                       // q bf16, pre-scaled
__device__ __align__(256) __nv_bfloat16 g_kTh[MTOT * DIM], g_kTl[MTOT * DIM];
__device__ __align__(256) __nv_bfloat16 g_vTh[MTOT * DIM], g_vTl[MTOT * DIM];
__device__ __align__(256) __nv_bfloat16 g_ah[MTOT * DIM], g_al[MTOT * DIM];
__device__ __align__(256) __nv_bfloat16 g_klh[BATCH * RLOW * DIM], g_kll[BATCH * RLOW * DIM];
__device__ __align__(256) __nv_bfloat16 g_vlh[BATCH * DIM * RLOW], g_vll[BATCH * DIM * RLOW];
__device__ __align__(256) __nv_bfloat16 g_wqh[3 * DIM * DIM], g_wql[3 * DIM * DIM];
__device__ __align__(256) __nv_bfloat16 g_wph[DIM * DIM], g_wpl[DIM * DIM];
__device__ __align__(256) __nv_bfloat16 g_Eh[RLOW * NSEQ], g_El[RLOW * NSEQ];
__device__ __align__(256) __nv_bfloat16 g_Fh[RLOW * NSEQ], g_Fl[RLOW * NSEQ];

// ================= helpers =================
__device__ __forceinline__ uint32_t smem_u32(const void* p) {
    uint32_t a;
    asm("{ .reg .u64 t; cvta.to.shared.u64 t, %1; cvt.u32.u64 %0, t; }" : "=r"(a) : "l"(p));
    return a;
}
__device__ __forceinline__ void ldsm4(uint32_t r[4], uint32_t a) {
    asm volatile("ldmatrix.sync.aligned.m8n8.x4.shared.b16 {%0,%1,%2,%3}, [%4];"
                 : "=r"(r[0]), "=r"(r[1]), "=r"(r[2]), "=r"(r[3]) : "r"(a));
}
__device__ __forceinline__ void mma16816(float* c, const uint32_t a[4], uint32_t b0, uint32_t b1) {
    asm volatile("mma.sync.aligned.m16n8k16.row.col.f32.bf16.bf16.f32 "
                 "{%0,%1,%2,%3},{%4,%5,%6,%7},{%8,%9},{%0,%1,%2,%3};"
                 : "+f"(c[0]), "+f"(c[1]), "+f"(c[2]), "+f"(c[3])
                 : "r"(a[0]), "r"(a[1]), "r"(a[2]), "r"(a[3]), "r"(b0), "r"(b1));
}
__device__ __forceinline__ void cpa16(uint32_t saddr, const void* g) {
    asm volatile("cp.async.ca.shared.global [%0], [%1], 16;" :: "r"(saddr), "l"(g));
}
#define CPA_COMMIT() asm volatile("cp.async.commit_group;" ::: "memory")
#define CPA_WAIT1()  asm volatile("cp.async.wait_group 1;" ::: "memory")
#define CPA_WAIT0()  asm volatile("cp.async.wait_group 0;" ::: "memory")

__device__ __forceinline__ void split_bf16(float v, __nv_bfloat16& h, __nv_bfloat16& l) {
    h = __float2bfloat16(v);
    l = __float2bfloat16(v - __bfloat162float(h));
}
__device__ __forceinline__ uint32_t pack_split(float e0, float e1, uint32_t& lo) {
    __nv_bfloat162 h = __floats2bfloat162_rn(e0, e1);
    float2 f = __bfloat1622float2(h);
    __nv_bfloat162 l = __floats2bfloat162_rn(e0 - f.x, e1 - f.y);
    lo = *reinterpret_cast<uint32_t*>(&l);
    return *reinterpret_cast<uint32_t*>(&h);
}

// ================= GEMM smem layout: K-chunk 32, 3 stages =================
#define ROWB   80
#define S_AL   10240
#define S_BH   20480
#define S_BL   25600
#define STG    30720
#define SOFF   512
#define SMEM_GEMM (SOFF + 3 * STG)   // 92672

__device__ __forceinline__ void compute_chunk(uint32_t st, int wm, int wn, int lane,
                                              float acc[2][4][4])
{
    uint32_t a0r = st + (wm * 32 + (lane & 15)) * ROWB + ((lane >> 4) & 1) * 16;
    uint32_t b0r = st + S_BH + (wn * 32 + (lane & 7) + ((lane >> 4) & 1) * 8) * ROWB
                   + ((lane >> 3) & 1) * 16;
#pragma unroll
    for (int ks = 0; ks < 2; ks++) {
        uint32_t ah[2][4], al[2][4], bhA[4], bhB[4], blA[4], blB[4];
        ldsm4(ah[0], a0r + ks * 32);
        ldsm4(ah[1], a0r + 16 * ROWB + ks * 32);
        ldsm4(al[0], a0r + S_AL + ks * 32);
        ldsm4(al[1], a0r + S_AL + 16 * ROWB + ks * 32);
        ldsm4(bhA, b0r + ks * 32);
        ldsm4(bhB, b0r + 16 * ROWB + ks * 32);
        ldsm4(blA, b0r + (S_BL - S_BH) + ks * 32);
        ldsm4(blB, b0r + (S_BL - S_BH) + 16 * ROWB + ks * 32);
        uint32_t bh[4][2] = {{bhA[0], bhA[1]}, {bhA[2], bhA[3]}, {bhB[0], bhB[1]}, {bhB[2], bhB[3]}};
        uint32_t bl[4][2] = {{blA[0], blA[1]}, {blA[2], blA[3]}, {blB[0], blB[1]}, {blB[2], blB[3]}};
#pragma unroll
        for (int mf = 0; mf < 2; mf++)
#pragma unroll
            for (int nf = 0; nf < 4; nf++) {
                mma16816(acc[mf][nf], ah[mf], bh[nf][0], bh[nf][1]);
                mma16816(acc[mf][nf], al[mf], bh[nf][0], bh[nf][1]);
                mma16816(acc[mf][nf], ah[mf], bl[nf][0], bl[nf][1]);
            }
    }
}

// ================= fused split conversion =================
#define N4X (MTOT * DIM / 4)            // 4816896
#define N4Q (3 * DIM * DIM / 4)         // 27648
#define N4E (RLOW * NSEQ / 4)           // 100352
#define N4P (DIM * DIM / 4)             // 9216
#define N4TOT (N4X + N4Q + 2 * N4E + N4P)
__global__ void split_all(const float* __restrict__ x, const float* __restrict__ qw,
                          const float* __restrict__ Ew, const float* __restrict__ Fw,
                          const float* __restrict__ pw)
{
    int i = blockIdx.x * blockDim.x + threadIdx.x;
    if (i >= N4TOT) return;
    const float* src;
    __nv_bfloat16 *hi, *lo;
    int off;
    if (i < N4X)                       { src = x;  hi = g_xh;  lo = g_xl;  off = i; }
    else if (i < N4X + N4Q)            { src = qw; hi = g_wqh; lo = g_wql; off = i - N4X; }
    else if (i < N4X + N4Q + N4E)      { src = Ew; hi = g_Eh;  lo = g_El;  off = i - N4X - N4Q; }
    else if (i < N4X + N4Q + 2 * N4E)  { src = Fw; hi = g_Fh;  lo = g_Fl;  off = i - N4X - N4Q - N4E; }
    else                               { src = pw; hi = g_wph; lo = g_wpl; off = i - N4X - N4Q - 2 * N4E; }
    float4 v = reinterpret_cast<const float4*>(src)[off];
    __nv_bfloat162 h01 = __floats2bfloat162_rn(v.x, v.y);
    __nv_bfloat162 h23 = __floats2bfloat162_rn(v.z, v.w);
    float2 f01 = __bfloat1622float2(h01), f23 = __bfloat1622float2(h23);
    __nv_bfloat162 l01 = __floats2bfloat162_rn(v.x - f01.x, v.y - f01.y);
    __nv_bfloat162 l23 = __floats2bfloat162_rn(v.z - f23.x, v.w - f23.y);
    reinterpret_cast<__nv_bfloat162*>(hi)[2 * off]     = h01;
    reinterpret_cast<__nv_bfloat162*>(hi)[2 * off + 1] = h23;
    reinterpret_cast<__nv_bfloat162*>(lo)[2 * off]     = l01;
    reinterpret_cast<__nv_bfloat162*>(lo)[2 * off + 1] = l23;
}

// ================= QKV: M=128 N=64 K=192 (6 chunks) =================
__global__ __launch_bounds__(256, 2) void qkv_mma(const float* __restrict__ bias)
{
    extern __shared__ char sm[];
    uint32_t sb = smem_u32(sm);
    const int t = threadIdx.x, lane = t & 31, wid = t >> 5;
    const int wm = wid & 3, wn = wid >> 2;
    const int m0 = blockIdx.x * 128, j0 = blockIdx.y * 64;
    int* rowoff = (int*)sm;

    if (t < 128) {
        int m   = m0 + t;
        int bb  = m / NSEQ, n = m - bb * NSEQ;
        int r56 = n / 56, c56 = n - r56 * 56;
        int hb  = r56 / 7, hi_ = r56 - hb * 7;
        int wb  = c56 / 7, wi = c56 - wb * 7;
        rowoff[t] = ((bb * 64 + hb * 8 + wb) * 49 + hi_ * 7 + wi) * DIM;
    }
    __syncthreads();

    auto issue = [&](int i) {
        uint32_t st = sb + SOFF + (i % 3) * STG;
        int k0 = i * 32;
#pragma unroll
        for (int l = 0; l < 2; l++) {
            int idx = t + 256 * l;
            int row = idx >> 2, cg = idx & 3;
            uint32_t so = row * ROWB + cg * 16;
            int gi = rowoff[row] + k0 + cg * 8;
            cpa16(st + so, g_xh + gi);
            cpa16(st + S_AL + so, g_xl + gi);
        }
        {
            int row = t >> 2, cg = t & 3;
            uint32_t so = row * ROWB + cg * 16;
            int gi = (j0 + row) * DIM + k0 + cg * 8;
            cpa16(st + S_BH + so, g_wqh + gi);
            cpa16(st + S_BL + so, g_wql + gi);
        }
        CPA_COMMIT();
    };

    float acc[2][4][4] = {};
    issue(0); issue(1);
    for (int i = 0; i < 6; i++) {
        if (i + 1 < 6) { CPA_WAIT1(); } else { CPA_WAIT0(); }
        __syncthreads();
        if (i + 2 < 6) issue(i + 2);
        compute_chunk(sb + SOFF + (i % 3) * STG, wm, wn, lane, acc);
    }
    __syncthreads();

    const int seg = j0 / DIM;          // 0=q 1=k 2=v
    const int jb  = j0 - seg * DIM;
    const float scale = 0.17677669529663687f;

    if (seg == 0) {
        // q: stage hi only, [n][c] stride 144
#pragma unroll
        for (int mf = 0; mf < 2; mf++)
#pragma unroll
            for (int rr = 0; rr < 2; rr++) {
                int ml = wm * 32 + mf * 16 + (lane >> 2) + rr * 8;
#pragma unroll
                for (int nf = 0; nf < 4; nf++)
#pragma unroll
                    for (int cp = 0; cp < 2; cp++) {
                        int c = wn * 32 + nf * 8 + (lane & 3) * 2 + cp;
                        float v = (acc[mf][nf][rr * 2 + cp] + bias[j0 + c]) * scale;
                        *(__nv_bfloat16*)(sm + SOFF + ml * 144 + c * 2) = __float2bfloat16(v);
                    }
            }
        __syncthreads();
        const int h0 = jb >> 5;
        {
            int row = t >> 1, q = t & 1;      // 256 tasks of 64B
            int m = m0 + row, b = m / NSEQ, n = m - b * NSEQ;
            const uint4* src = (const uint4*)(sm + SOFF + row * 144 + q * 64);
            __nv_bfloat16* dst = g_qh + ((b * HEADS + h0 + q) * NSEQ + n) * HD;
#pragma unroll
            for (int u = 0; u < 4; u++) ((uint4*)dst)[u] = src[u];
        }
    } else {
        // k/v transposed: stage [c][n], stride 272
#pragma unroll
        for (int mf = 0; mf < 2; mf++)
#pragma unroll
            for (int rr = 0; rr < 2; rr++) {
                int ml = wm * 32 + mf * 16 + (lane >> 2) + rr * 8;
#pragma unroll
                for (int nf = 0; nf < 4; nf++)
#pragma unroll
                    for (int cp = 0; cp < 2; cp++) {
                        int c = wn * 32 + nf * 8 + (lane & 3) * 2 + cp;
                        float v = acc[mf][nf][rr * 2 + cp] + bias[j0 + c];
                        __nv_bfloat16 h_, l_;
                        split_bf16(v, h_, l_);
                        *(__nv_bfloat16*)(sm + SOFF + c * 272 + ml * 2) = h_;
                        *(__nv_bfloat16*)(sm + SOFF + 17408 + c * 272 + ml * 2) = l_;
                    }
            }
        __syncthreads();
        __nv_bfloat16* H = (seg == 1) ? g_kTh : g_vTh;
        __nv_bfloat16* L = (seg == 1) ? g_kTl : g_vTl;
#pragma unroll
        for (int l = 0; l < 8; l++) {
            int idx = t + 256 * l;             // 2048 uint4
            int row = idx >> 4, g = idx & 15;
            int hl = row >> 6, c = row & 63;
            int m = m0 + g * 8, b = m / NSEQ, n = m - b * NSEQ;
            uint4 v = *(const uint4*)(sm + SOFF + hl * 17408 + c * 272 + g * 16);
            *(uint4*)((hl ? L : H) + (b * DIM + jb + c) * NSEQ + n) = v;
        }
    }
}

// ================= low-rank: M=128 N=64 K=3136 (98 chunks) =================
__global__ __launch_bounds__(256, 2) void lowrank_mma(const float* __restrict__ Eb,
                                                      const float* __restrict__ Fb)
{
    extern __shared__ char sm[];
    uint32_t sb = smem_u32(sm);
    const int t = threadIdx.x, lane = t & 31, wid = t >> 5;
    const int wm = wid & 3, wn = wid >> 2;
    const int c0 = blockIdx.x * 64, b = blockIdx.y, which = blockIdx.z;

    const __nv_bfloat16* Ah = which ? g_Fh : g_Eh;
    const __nv_bfloat16* Al = which ? g_Fl : g_El;
    const __nv_bfloat16* Bh = which ? g_vTh : g_kTh;
    const __nv_bfloat16* Bl = which ? g_vTl : g_kTl;
    const float* bias = which ? Fb : Eb;

    auto issue = [&](int i) {
        uint32_t st = sb + SOFF + (i % 3) * STG;
        int k0 = i * 32;
#pragma unroll
        for (int l = 0; l < 2; l++) {
            int idx = t + 256 * l;
            int row = idx >> 2, cg = idx & 3;
            uint32_t so = row * ROWB + cg * 16;
            int gi = row * NSEQ + k0 + cg * 8;
            cpa16(st + so, Ah + gi);
            cpa16(st + S_AL + so, Al + gi);
        }
        {
            int row = t >> 2, cg = t & 3;
            uint32_t so = row * ROWB + cg * 16;
            int gi = (b * DIM + c0 + row) * NSEQ + k0 + cg * 8;
            cpa16(st + S_BH + so, Bh + gi);
            cpa16(st + S_BL + so, Bl + gi);
        }
        CPA_COMMIT();
    };

    float acc[2][4][4] = {};
    issue(0); issue(1);
    for (int i = 0; i < 98; i++) {
        if (i + 1 < 98) { CPA_WAIT1(); } else { CPA_WAIT0(); }
        __syncthreads();
        if (i + 2 < 98) issue(i + 2);
        compute_chunk(sb + SOFF + (i % 3) * STG, wm, wn, lane, acc);
    }
    __syncthreads();

    if (which == 0) {
#pragma unroll
        for (int mf = 0; mf < 2; mf++)
#pragma unroll
            for (int rr = 0; rr < 2; rr++) {
                int r = wm * 32 + mf * 16 + (lane >> 2) + rr * 8;
                float bv = bias[r];
#pragma unroll
                for (int nf = 0; nf < 4; nf++)
#pragma unroll
                    for (int cp = 0; cp < 2; cp++) {
                        int c = wn * 32 + nf * 8 + (lane & 3) * 2 + cp;
                        float v = acc[mf][nf][rr * 2 + cp] + bv;
                        __nv_bfloat16 h_, l_;
                        split_bf16(v, h_, l_);
                        *(__nv_bfloat16*)(sm + SOFF + r * 144 + c * 2) = h_;
                        *(__nv_bfloat16*)(sm + SOFF + 18432 + r * 144 + c * 2) = l_;
                    }
            }
        __syncthreads();
#pragma unroll
        for (int l = 0; l < 2; l++) {
            int idx = t + 256 * l;             // 512 tasks of 64B
            int hl = idx >> 8, rem = idx & 255;
            int r = rem >> 1, half = rem & 1;
            const uint4* src = (const uint4*)(sm + SOFF + hl * 18432 + r * 144 + half * 64);
            __nv_bfloat16* dst = (hl ? g_kll : g_klh) + (b * RLOW + r) * DIM + c0 + half * 32;
#pragma unroll
            for (int u = 0; u < 4; u++) ((uint4*)dst)[u] = src[u];
        }
    } else {
#pragma unroll
        for (int mf = 0; mf < 2; mf++)
#pragma unroll
            for (int rr = 0; rr < 2; rr++) {
                int r = wm * 32 + mf * 16 + (lane >> 2) + rr * 8;
                float bv = bias[r];
#pragma unroll
                for (int nf = 0; nf < 4; nf++)
#pragma unroll
                    for (int cp = 0; cp < 2; cp++) {
                        int c = wn * 32 + nf * 8 + (lane & 3) * 2 + cp;
                        float v = acc[mf][nf][rr * 2 + cp] + bv;
                        __nv_bfloat16 h_, l_;
                        split_bf16(v, h_, l_);
                        *(__nv_bfloat16*)(sm + SOFF + c * 272 + r * 2) = h_;
                        *(__nv_bfloat16*)(sm + SOFF + 17408 + c * 272 + r * 2) = l_;
                    }
            }
        __syncthreads();
#pragma unroll
        for (int l = 0; l < 8; l++) {
            int idx = t + 256 * l;             // 2048 uint4
            int row = idx >> 4, g = idx & 15;
            int hl = row >> 6, c = row & 63;
            uint4 v = *(const uint4*)(sm + SOFF + hl * 17408 + c * 272 + g * 16);
            *(uint4*)((hl ? g_vll : g_vlh) + (b * DIM + c0 + c) * RLOW + g * 8) = v;
        }
    }
}

// ================= attention: q in plain bf16 (2-term phase-1) =================
#define AQ_H 0
#define AK_H 5120
#define AK_L 15360
#define AV_H 25600
#define AV_L 34304
#define ATT_SMEM 43008
__global__ __launch_bounds__(128) void attn_mma()
{
    extern __shared__ char sm[];
    uint32_t sb = smem_u32(sm);
    const int t = threadIdx.x, lane = t & 31, w = t >> 5;
    const int n0 = blockIdx.x * 64, hh = blockIdx.y, b = blockIdx.z;

    {
        const __nv_bfloat16* qh = g_qh + ((b * HEADS + hh) * NSEQ + n0) * HD;
#pragma unroll
        for (int l = 0; l < 2; l++) {
            int idx = t + 128 * l;
            int row = idx >> 2, cg = idx & 3;
            *(uint4*)(sm + AQ_H + row * 80 + cg * 16) = *(const uint4*)(qh + row * HD + cg * 8);
        }
        const __nv_bfloat16* kh = g_klh + b * RLOW * DIM + hh * HD;
        const __nv_bfloat16* kl = g_kll + b * RLOW * DIM + hh * HD;
#pragma unroll
        for (int l = 0; l < 4; l++) {
            int idx = t + 128 * l;
            int row = idx >> 2, cg = idx & 3;
            *(uint4*)(sm + AK_H + row * 80 + cg * 16) = *(const uint4*)(kh + row * DIM + cg * 8);
            *(uint4*)(sm + AK_L + row * 80 + cg * 16) = *(const uint4*)(kl + row * DIM + cg * 8);
        }
        const __nv_bfloat16* vh = g_vlh + (b * DIM + hh * HD) * RLOW;
        const __nv_bfloat16* vl = g_vll + (b * DIM + hh * HD) * RLOW;
#pragma unroll
        for (int l = 0; l < 4; l++) {
            int idx = t + 128 * l;
            int row = idx >> 4, cg = idx & 15;
            *(uint4*)(sm + AV_H + row * 272 + cg * 16) = *(const uint4*)(vh + row * RLOW + cg * 8);
            *(uint4*)(sm + AV_L + row * 272 + cg * 16) = *(const uint4*)(vl + row * RLOW + cg * 8);
        }
    }
    __syncthreads();

    // phase 1: logits = qh·(klow_hi + klow_lo)  (2-term)
    float acc[16][4] = {};
    {
        uint32_t qa = sb + AQ_H + (w * 16 + (lane & 15)) * 80 + ((lane >> 4) & 1) * 16;
        uint32_t ba = sb + AK_H + ((lane & 7) + ((lane >> 4) & 1) * 8) * 80 + ((lane >> 3) & 1) * 16;
#pragma unroll
        for (int ks = 0; ks < 2; ks++) {
            uint32_t aH[4];
            ldsm4(aH, qa + ks * 32);
#pragma unroll
            for (int np = 0; np < 8; np++) {
                uint32_t bh[4], bl[4];
                ldsm4(bh, ba + np * 1280 + ks * 32);
                ldsm4(bl, ba + (AK_L - AK_H) + np * 1280 + ks * 32);
                mma16816(acc[2 * np], aH, bh[0], bh[1]);
                mma16816(acc[2 * np], aH, bl[0], bl[1]);
                mma16816(acc[2 * np + 1], aH, bh[2], bh[3]);
                mma16816(acc[2 * np + 1], aH, bl[2], bl[3]);
            }
        }
    }

    float m0 = -1e30f, m1 = -1e30f;
#pragma unroll
    for (int i = 0; i < 16; i++) {
        m0 = fmaxf(m0, fmaxf(acc[i][0], acc[i][1]));
        m1 = fmaxf(m1, fmaxf(acc[i][2], acc[i][3]));
    }
    m0 = fmaxf(m0, __shfl_xor_sync(0xffffffff, m0, 1));
    m0 = fmaxf(m0, __shfl_xor_sync(0xffffffff, m0, 2));
    m1 = fmaxf(m1, __shfl_xor_sync(0xffffffff, m1, 1));
    m1 = fmaxf(m1, __shfl_xor_sync(0xffffffff, m1, 2));
    float s0 = 0.f, s1 = 0.f;
#pragma unroll
    for (int i = 0; i < 16; i++) {
        acc[i][0] = __expf(acc[i][0] - m0); s0 += acc[i][0];
        acc[i][1] = __expf(acc[i][1] - m0); s0 += acc[i][1];
        acc[i][2] = __expf(acc[i][2] - m1); s1 += acc[i][2];
        acc[i][3] = __expf(acc[i][3] - m1); s1 += acc[i][3];
    }
    s0 += __shfl_xor_sync(0xffffffff, s0, 1);
    s0 += __shfl_xor_sync(0xffffffff, s0, 2);
    s1 += __shfl_xor_sync(0xffffffff, s1, 1);
    s1 += __shfl_xor_sync(0xffffffff, s1, 2);

    // phase 3: out = attn @ vlow (3-term)
    float oacc[4][4] = {};
    {
        uint32_t va = sb + AV_H + ((lane & 7) + ((lane >> 4) & 1) * 8) * 272 + ((lane >> 3) & 1) * 16;
#pragma unroll
        for (int kt = 0; kt < 8; kt++) {
            uint32_t ah[4], al[4];
            ah[0] = pack_split(acc[2 * kt][0],     acc[2 * kt][1],     al[0]);
            ah[1] = pack_split(acc[2 * kt][2],     acc[2 * kt][3],     al[1]);
            ah[2] = pack_split(acc[2 * kt + 1][0], acc[2 * kt + 1][1], al[2]);
            ah[3] = pack_split(acc[2 * kt + 1][2], acc[2 * kt + 1][3], al[3]);
#pragma unroll
            for (int np = 0; np < 2; np++) {
                uint32_t vh[4], vl[4];
                ldsm4(vh, va + np * 16 * 272 + kt * 32);
                ldsm4(vl, va + (AV_L - AV_H) + np * 16 * 272 + kt * 32);
                mma16816(oacc[2 * np], ah, vh[0], vh[1]);
                mma16816(oacc[2 * np], al, vh[0], vh[1]);
                mma16816(oacc[2 * np], ah, vl[0], vl[1]);
                mma16816(oacc[2 * np + 1], ah, vh[2], vh[3]);
                mma16816(oacc[2 * np + 1], al, vh[2], vh[3]);
                mma16816(oacc[2 * np + 1], ah, vl[2], vl[3]);
            }
        }
    }

    {
        float inv0 = 1.0f / s0, inv1 = 1.0f / s1;
        int gr = lane >> 2;
        int row0 = n0 + w * 16 + gr, row1 = row0 + 8;
        int cbase = hh * HD + (lane & 3) * 2;
#pragma unroll
        for (int nf = 0; nf < 4; nf++) {
            int col = cbase + nf * 8;
            __nv_bfloat16 h_, l_;
            float v;
            v = oacc[nf][0] * inv0; split_bf16(v, h_, l_);
            g_ah[(b * NSEQ + row0) * DIM + col] = h_;     g_al[(b * NSEQ + row0) * DIM + col] = l_;
            v = oacc[nf][1] * inv0; split_bf16(v, h_, l_);
            g_ah[(b * NSEQ + row0) * DIM + col + 1] = h_; g_al[(b * NSEQ + row0) * DIM + col + 1] = l_;
            v = oacc[nf][2] * inv1; split_bf16(v, h_, l_);
            g_ah[(b * NSEQ + row1) * DIM + col] = h_;     g_al[(b * NSEQ + row1) * DIM + col] = l_;
            v = oacc[nf][3] * inv1; split_bf16(v, h_, l_);
            g_ah[(b * NSEQ + row1) * DIM + col + 1] = h_; g_al[(b * NSEQ + row1) * DIM + col + 1] = l_;
        }
    }
}

// ================= proj: M=128 N=64 K=192 (6 chunks) =================
__global__ __launch_bounds__(256, 2) void proj_mma(const float* __restrict__ bias,
                                                   float* __restrict__ out)
{
    extern __shared__ char sm[];
    uint32_t sb = smem_u32(sm);
    const int t = threadIdx.x, lane = t & 31, wid = t >> 5;
    const int wm = wid & 3, wn = wid >> 2;
    const int m0 = blockIdx.x * 128, j0 = blockIdx.y * 64;

    auto issue = [&](int i) {
        uint32_t st = sb + SOFF + (i % 3) * STG;
        int k0 = i * 32;
#pragma unroll
        for (int l = 0; l < 2; l++) {
            int idx = t + 256 * l;
            int row = idx >> 2, cg = idx & 3;
            uint32_t so = row * ROWB + cg * 16;
            int gi = (m0 + row) * DIM + k0 + cg * 8;
            cpa16(st + so, g_ah + gi);
            cpa16(st + S_AL + so, g_al + gi);
        }
        {
            int row = t >> 2, cg = t & 3;
            uint32_t so = row * ROWB + cg * 16;
            int gi = (j0 + row) * DIM + k0 + cg * 8;
            cpa16(st + S_BH + so, g_wph + gi);
            cpa16(st + S_BL + so, g_wpl + gi);
        }
        CPA_COMMIT();
    };

    float acc[2][4][4] = {};
    issue(0); issue(1);
    for (int i = 0; i < 6; i++) {
        if (i + 1 < 6) { CPA_WAIT1(); } else { CPA_WAIT0(); }
        __syncthreads();
        if (i + 2 < 6) issue(i + 2);
        compute_chunk(sb + SOFF + (i % 3) * STG, wm, wn, lane, acc);
    }
    __syncthreads();

#pragma unroll
    for (int mf = 0; mf < 2; mf++)
#pragma unroll
        for (int rr = 0; rr < 2; rr++) {
            int ml = wm * 32 + mf * 16 + (lane >> 2) + rr * 8;
#pragma unroll
            for (int nf = 0; nf < 4; nf++)
#pragma unroll
                for (int cp = 0; cp < 2; cp++) {
                    int c = wn * 32 + nf * 8 + (lane & 3) * 2 + cp;
                    *(float*)(sm + SOFF + ml * 272 + c * 4) =
                        acc[mf][nf][rr * 2 + cp] + bias[j0 + c];
                }
        }
    __syncthreads();
#pragma unroll
    for (int l = 0; l < 8; l++) {
        int idx = t + 256 * l;
        int row = idx >> 4, g = idx & 15;
        uint4 v = *(const uint4*)(sm + SOFF + row * 272 + g * 16);
        *(uint4*)(out + (m0 + row) * DIM + j0 + g * 4) = v;
    }
}

// ================= host =================
extern "C" void kernel_launch(void* const* d_in, const int* in_sizes, int n_in,
                              void* d_out, int out_size)
{
    const float* x      = (const float*)d_in[0];
    const float* qkv_w  = (const float*)d_in[1];
    const float* qkv_b  = (const float*)d_in[2];
    const float* E_w    = (const float*)d_in[3];
    const float* E_b    = (const float*)d_in[4];
    const float* F_w    = (const float*)d_in[5];
    const float* F_b    = (const float*)d_in[6];
    const float* proj_w = (const float*)d_in[7];
    const float* proj_b = (const float*)d_in[8];
    float* out = (float*)d_out;

    cudaFuncSetAttribute(qkv_mma, cudaFuncAttributeMaxDynamicSharedMemorySize, SMEM_GEMM);
    cudaFuncSetAttribute(lowrank_mma, cudaFuncAttributeMaxDynamicSharedMemorySize, SMEM_GEMM);
    cudaFuncSetAttribute(proj_mma, cudaFuncAttributeMaxDynamicSharedMemorySize, SMEM_GEMM);
    cudaFuncSetAttribute(attn_mma, cudaFuncAttributeMaxDynamicSharedMemorySize, ATT_SMEM);

    split_all<<<(N4TOT + 255) / 256, 256>>>(x, qkv_w, E_w, F_w, proj_w);
    qkv_mma<<<dim3(MTOT / 128, 9), 256, SMEM_GEMM>>>(qkv_b);
    lowrank_mma<<<dim3(3, BATCH, 2), 256, SMEM_GEMM>>>(E_b, F_b);
    attn_mma<<<dim3(NSEQ / 64, HEADS, BATCH), 128, ATT_SMEM>>>();
    proj_mma<<<dim3(MTOT / 128, 3), 256, SMEM_GEMM>>>(proj_b, out);
}

// round 7
// speedup vs baseline: 1.0843x; 1.0843x over previous
#include <cuda_runtime.h>
#include <cuda_bf16.h>
#include <cstdint>
#include <math.h>

#define DIM   192
#define HEADS 6
#define HD    32
#define RLOW  128
#define NSEQ  3136
#define BATCH 32
#define MTOT  (BATCH * NSEQ)   // 100352

// ================= scratch (device globals) =================
__device__ __align__(256) __nv_bfloat16 g_xh[MTOT * DIM], g_xl[MTOT * DIM];
__device__ __align__(256) __nv_bfloat16 g_qh[MTOT * DIM];                       // q bf16, pre-scaled
__device__ __align__(256) __nv_bfloat16 g_kTh[MTOT * DIM], g_kTl[MTOT * DIM];
__device__ __align__(256) __nv_bfloat16 g_vTh[MTOT * DIM], g_vTl[MTOT * DIM];
__device__ __align__(256) __nv_bfloat16 g_ah[MTOT * DIM], g_al[MTOT * DIM];
__device__ __align__(256) __nv_bfloat16 g_klh[BATCH * RLOW * DIM], g_kll[BATCH * RLOW * DIM];
__device__ __align__(256) __nv_bfloat16 g_vlh[BATCH * DIM * RLOW], g_vll[BATCH * DIM * RLOW];
__device__ __align__(256) __nv_bfloat16 g_wqh[3 * DIM * DIM], g_wql[3 * DIM * DIM];
__device__ __align__(256) __nv_bfloat16 g_wph[DIM * DIM], g_wpl[DIM * DIM];
__device__ __align__(256) __nv_bfloat16 g_Eh[RLOW * NSEQ], g_El[RLOW * NSEQ];
__device__ __align__(256) __nv_bfloat16 g_Fh[RLOW * NSEQ], g_Fl[RLOW * NSEQ];

// ================= helpers =================
__device__ __forceinline__ uint32_t smem_u32(const void* p) {
    uint32_t a;
    asm("{ .reg .u64 t; cvta.to.shared.u64 t, %1; cvt.u32.u64 %0, t; }" : "=r"(a) : "l"(p));
    return a;
}
__device__ __forceinline__ void ldsm4(uint32_t r[4], uint32_t a) {
    asm volatile("ldmatrix.sync.aligned.m8n8.x4.shared.b16 {%0,%1,%2,%3}, [%4];"
                 : "=r"(r[0]), "=r"(r[1]), "=r"(r[2]), "=r"(r[3]) : "r"(a));
}
__device__ __forceinline__ void mma16816(float* c, const uint32_t a[4], uint32_t b0, uint32_t b1) {
    asm volatile("mma.sync.aligned.m16n8k16.row.col.f32.bf16.bf16.f32 "
                 "{%0,%1,%2,%3},{%4,%5,%6,%7},{%8,%9},{%0,%1,%2,%3};"
                 : "+f"(c[0]), "+f"(c[1]), "+f"(c[2]), "+f"(c[3])
                 : "r"(a[0]), "r"(a[1]), "r"(a[2]), "r"(a[3]), "r"(b0), "r"(b1));
}
__device__ __forceinline__ void cpa16(uint32_t saddr, const void* g) {
    asm volatile("cp.async.ca.shared.global [%0], [%1], 16;" :: "r"(saddr), "l"(g));
}
#define CPA_COMMIT() asm volatile("cp.async.commit_group;" ::: "memory")
#define CPA_WAIT1()  asm volatile("cp.async.wait_group 1;" ::: "memory")
#define CPA_WAIT0()  asm volatile("cp.async.wait_group 0;" ::: "memory")

__device__ __forceinline__ void split_bf16(float v, __nv_bfloat16& h, __nv_bfloat16& l) {
    h = __float2bfloat16(v);
    l = __float2bfloat16(v - __bfloat162float(h));
}
__device__ __forceinline__ uint32_t pack_split(float e0, float e1, uint32_t& lo) {
    __nv_bfloat162 h = __floats2bfloat162_rn(e0, e1);
    float2 f = __bfloat1622float2(h);
    __nv_bfloat162 l = __floats2bfloat162_rn(e0 - f.x, e1 - f.y);
    lo = *reinterpret_cast<uint32_t*>(&l);
    return *reinterpret_cast<uint32_t*>(&h);
}

// ================= GEMM smem layout: K-chunk 32, 2 stages (R5-proven) =================
#define ROWB   80
#define S_AL   10240
#define S_BH   20480
#define S_BL   25600
#define STG    30720
#define SOFF   512
#define SMEM_GEMM (SOFF + 2 * STG)   // 61952

__device__ __forceinline__ void compute_chunk(uint32_t st, int wm, int wn, int lane,
                                              float acc[2][4][4])
{
    uint32_t a0r = st + (wm * 32 + (lane & 15)) * ROWB + ((lane >> 4) & 1) * 16;
    uint32_t b0r = st + S_BH + (wn * 32 + (lane & 7) + ((lane >> 4) & 1) * 8) * ROWB
                   + ((lane >> 3) & 1) * 16;
#pragma unroll
    for (int ks = 0; ks < 2; ks++) {
        uint32_t ah[2][4], al[2][4], bhA[4], bhB[4], blA[4], blB[4];
        ldsm4(ah[0], a0r + ks * 32);
        ldsm4(ah[1], a0r + 16 * ROWB + ks * 32);
        ldsm4(al[0], a0r + S_AL + ks * 32);
        ldsm4(al[1], a0r + S_AL + 16 * ROWB + ks * 32);
        ldsm4(bhA, b0r + ks * 32);
        ldsm4(bhB, b0r + 16 * ROWB + ks * 32);
        ldsm4(blA, b0r + (S_BL - S_BH) + ks * 32);
        ldsm4(blB, b0r + (S_BL - S_BH) + 16 * ROWB + ks * 32);
        uint32_t bh[4][2] = {{bhA[0], bhA[1]}, {bhA[2], bhA[3]}, {bhB[0], bhB[1]}, {bhB[2], bhB[3]}};
        uint32_t bl[4][2] = {{blA[0], blA[1]}, {blA[2], blA[3]}, {blB[0], blB[1]}, {blB[2], blB[3]}};
#pragma unroll
        for (int mf = 0; mf < 2; mf++)
#pragma unroll
            for (int nf = 0; nf < 4; nf++) {
                mma16816(acc[mf][nf], ah[mf], bh[nf][0], bh[nf][1]);
                mma16816(acc[mf][nf], al[mf], bh[nf][0], bh[nf][1]);
                mma16816(acc[mf][nf], ah[mf], bl[nf][0], bl[nf][1]);
            }
    }
}

// ================= fused split conversion =================
#define N4X (MTOT * DIM / 4)
#define N4Q (3 * DIM * DIM / 4)
#define N4E (RLOW * NSEQ / 4)
#define N4P (DIM * DIM / 4)
#define N4TOT (N4X + N4Q + 2 * N4E + N4P)
__global__ void split_all(const float* __restrict__ x, const float* __restrict__ qw,
                          const float* __restrict__ Ew, const float* __restrict__ Fw,
                          const float* __restrict__ pw)
{
    int i = blockIdx.x * blockDim.x + threadIdx.x;
    if (i >= N4TOT) return;
    const float* src;
    __nv_bfloat16 *hi, *lo;
    int off;
    if (i < N4X)                       { src = x;  hi = g_xh;  lo = g_xl;  off = i; }
    else if (i < N4X + N4Q)            { src = qw; hi = g_wqh; lo = g_wql; off = i - N4X; }
    else if (i < N4X + N4Q + N4E)      { src = Ew; hi = g_Eh;  lo = g_El;  off = i - N4X - N4Q; }
    else if (i < N4X + N4Q + 2 * N4E)  { src = Fw; hi = g_Fh;  lo = g_Fl;  off = i - N4X - N4Q - N4E; }
    else                               { src = pw; hi = g_wph; lo = g_wpl; off = i - N4X - N4Q - 2 * N4E; }
    float4 v = reinterpret_cast<const float4*>(src)[off];
    __nv_bfloat162 h01 = __floats2bfloat162_rn(v.x, v.y);
    __nv_bfloat162 h23 = __floats2bfloat162_rn(v.z, v.w);
    float2 f01 = __bfloat1622float2(h01), f23 = __bfloat1622float2(h23);
    __nv_bfloat162 l01 = __floats2bfloat162_rn(v.x - f01.x, v.y - f01.y);
    __nv_bfloat162 l23 = __floats2bfloat162_rn(v.z - f23.x, v.w - f23.y);
    reinterpret_cast<__nv_bfloat162*>(hi)[2 * off]     = h01;
    reinterpret_cast<__nv_bfloat162*>(hi)[2 * off + 1] = h23;
    reinterpret_cast<__nv_bfloat162*>(lo)[2 * off]     = l01;
    reinterpret_cast<__nv_bfloat162*>(lo)[2 * off + 1] = l23;
}

// ================= QKV: M=128 N=64 K=192 (6 chunks) =================
__global__ __launch_bounds__(256, 2) void qkv_mma(const float* __restrict__ bias)
{
    extern __shared__ char sm[];
    uint32_t sb = smem_u32(sm);
    const int t = threadIdx.x, lane = t & 31, wid = t >> 5;
    const int wm = wid & 3, wn = wid >> 2;
    const int m0 = blockIdx.x * 128, j0 = blockIdx.y * 64;
    int* rowoff = (int*)sm;

    if (t < 128) {
        int m   = m0 + t;
        int bb  = m / NSEQ, n = m - bb * NSEQ;
        int r56 = n / 56, c56 = n - r56 * 56;
        int hb  = r56 / 7, hi_ = r56 - hb * 7;
        int wb  = c56 / 7, wi = c56 - wb * 7;
        rowoff[t] = ((bb * 64 + hb * 8 + wb) * 49 + hi_ * 7 + wi) * DIM;
    }
    __syncthreads();

    auto issue = [&](int i) {
        uint32_t st = sb + SOFF + (i & 1) * STG;
        int k0 = i * 32;
#pragma unroll
        for (int l = 0; l < 2; l++) {
            int idx = t + 256 * l;
            int row = idx >> 2, cg = idx & 3;
            uint32_t so = row * ROWB + cg * 16;
            int gi = rowoff[row] + k0 + cg * 8;
            cpa16(st + so, g_xh + gi);
            cpa16(st + S_AL + so, g_xl + gi);
        }
        {
            int row = t >> 2, cg = t & 3;
            uint32_t so = row * ROWB + cg * 16;
            int gi = (j0 + row) * DIM + k0 + cg * 8;
            cpa16(st + S_BH + so, g_wqh + gi);
            cpa16(st + S_BL + so, g_wql + gi);
        }
        CPA_COMMIT();
    };

    float acc[2][4][4] = {};
    issue(0);
    for (int i = 0; i < 6; i++) {
        if (i < 5) { issue(i + 1); CPA_WAIT1(); } else { CPA_WAIT0(); }
        __syncthreads();
        compute_chunk(sb + SOFF + (i & 1) * STG, wm, wn, lane, acc);
        __syncthreads();
    }

    const int seg = j0 / DIM;          // 0=q 1=k 2=v
    const int jb  = j0 - seg * DIM;
    const float scale = 0.17677669529663687f;

    if (seg == 0) {
        // q: stage hi only, [n][c] stride 144
#pragma unroll
        for (int mf = 0; mf < 2; mf++)
#pragma unroll
            for (int rr = 0; rr < 2; rr++) {
                int ml = wm * 32 + mf * 16 + (lane >> 2) + rr * 8;
#pragma unroll
                for (int nf = 0; nf < 4; nf++)
#pragma unroll
                    for (int cp = 0; cp < 2; cp++) {
                        int c = wn * 32 + nf * 8 + (lane & 3) * 2 + cp;
                        float v = (acc[mf][nf][rr * 2 + cp] + bias[j0 + c]) * scale;
                        *(__nv_bfloat16*)(sm + SOFF + ml * 144 + c * 2) = __float2bfloat16(v);
                    }
            }
        __syncthreads();
        const int h0 = jb >> 5;
        {
            int row = t >> 1, q = t & 1;      // 256 tasks of 64B
            int m = m0 + row, b = m / NSEQ, n = m - b * NSEQ;
            const uint4* src = (const uint4*)(sm + SOFF + row * 144 + q * 64);
            __nv_bfloat16* dst = g_qh + ((b * HEADS + h0 + q) * NSEQ + n) * HD;
#pragma unroll
            for (int u = 0; u < 4; u++) ((uint4*)dst)[u] = src[u];
        }
    } else {
        // k/v transposed: stage [c][n], stride 272
#pragma unroll
        for (int mf = 0; mf < 2; mf++)
#pragma unroll
            for (int rr = 0; rr < 2; rr++) {
                int ml = wm * 32 + mf * 16 + (lane >> 2) + rr * 8;
#pragma unroll
                for (int nf = 0; nf < 4; nf++)
#pragma unroll
                    for (int cp = 0; cp < 2; cp++) {
                        int c = wn * 32 + nf * 8 + (lane & 3) * 2 + cp;
                        float v = acc[mf][nf][rr * 2 + cp] + bias[j0 + c];
                        __nv_bfloat16 h_, l_;
                        split_bf16(v, h_, l_);
                        *(__nv_bfloat16*)(sm + SOFF + c * 272 + ml * 2) = h_;
                        *(__nv_bfloat16*)(sm + SOFF + 17408 + c * 272 + ml * 2) = l_;
                    }
            }
        __syncthreads();
        __nv_bfloat16* H = (seg == 1) ? g_kTh : g_vTh;
        __nv_bfloat16* L = (seg == 1) ? g_kTl : g_vTl;
#pragma unroll
        for (int l = 0; l < 8; l++) {
            int idx = t + 256 * l;             // 2048 uint4
            int row = idx >> 4, g = idx & 15;
            int hl = row >> 6, c = row & 63;
            int m = m0 + g * 8, b = m / NSEQ, n = m - b * NSEQ;
            uint4 v = *(const uint4*)(sm + SOFF + hl * 17408 + c * 272 + g * 16);
            *(uint4*)((hl ? L : H) + (b * DIM + jb + c) * NSEQ + n) = v;
        }
    }
}

// ================= low-rank: M=128 N=64 K=3136 (98 chunks) =================
__global__ __launch_bounds__(256, 2) void lowrank_mma(const float* __restrict__ Eb,
                                                      const float* __restrict__ Fb)
{
    extern __shared__ char sm[];
    uint32_t sb = smem_u32(sm);
    const int t = threadIdx.x, lane = t & 31, wid = t >> 5;
    const int wm = wid & 3, wn = wid >> 2;
    const int c0 = blockIdx.x * 64, b = blockIdx.y, which = blockIdx.z;

    const __nv_bfloat16* Ah = which ? g_Fh : g_Eh;
    const __nv_bfloat16* Al = which ? g_Fl : g_El;
    const __nv_bfloat16* Bh = which ? g_vTh : g_kTh;
    const __nv_bfloat16* Bl = which ? g_vTl : g_kTl;
    const float* bias = which ? Fb : Eb;

    auto issue = [&](int i) {
        uint32_t st = sb + SOFF + (i & 1) * STG;
        int k0 = i * 32;
#pragma unroll
        for (int l = 0; l < 2; l++) {
            int idx = t + 256 * l;
            int row = idx >> 2, cg = idx & 3;
            uint32_t so = row * ROWB + cg * 16;
            int gi = row * NSEQ + k0 + cg * 8;
            cpa16(st + so, Ah + gi);
            cpa16(st + S_AL + so, Al + gi);
        }
        {
            int row = t >> 2, cg = t & 3;
            uint32_t so = row * ROWB + cg * 16;
            int gi = (b * DIM + c0 + row) * NSEQ + k0 + cg * 8;
            cpa16(st + S_BH + so, Bh + gi);
            cpa16(st + S_BL + so, Bl + gi);
        }
        CPA_COMMIT();
    };

    float acc[2][4][4] = {};
    issue(0);
    for (int i = 0; i < 98; i++) {
        if (i < 97) { issue(i + 1); CPA_WAIT1(); } else { CPA_WAIT0(); }
        __syncthreads();
        compute_chunk(sb + SOFF + (i & 1) * STG, wm, wn, lane, acc);
        __syncthreads();
    }

    if (which == 0) {
#pragma unroll
        for (int mf = 0; mf < 2; mf++)
#pragma unroll
            for (int rr = 0; rr < 2; rr++) {
                int r = wm * 32 + mf * 16 + (lane >> 2) + rr * 8;
                float bv = bias[r];
#pragma unroll
                for (int nf = 0; nf < 4; nf++)
#pragma unroll
                    for (int cp = 0; cp < 2; cp++) {
                        int c = wn * 32 + nf * 8 + (lane & 3) * 2 + cp;
                        float v = acc[mf][nf][rr * 2 + cp] + bv;
                        __nv_bfloat16 h_, l_;
                        split_bf16(v, h_, l_);
                        *(__nv_bfloat16*)(sm + SOFF + r * 144 + c * 2) = h_;
                        *(__nv_bfloat16*)(sm + SOFF + 18432 + r * 144 + c * 2) = l_;
                    }
            }
        __syncthreads();
#pragma unroll
        for (int l = 0; l < 2; l++) {
            int idx = t + 256 * l;             // 512 tasks of 64B
            int hl = idx >> 8, rem = idx & 255;
            int r = rem >> 1, half = rem & 1;
            const uint4* src = (const uint4*)(sm + SOFF + hl * 18432 + r * 144 + half * 64);
            __nv_bfloat16* dst = (hl ? g_kll : g_klh) + (b * RLOW + r) * DIM + c0 + half * 32;
#pragma unroll
            for (int u = 0; u < 4; u++) ((uint4*)dst)[u] = src[u];
        }
    } else {
#pragma unroll
        for (int mf = 0; mf < 2; mf++)
#pragma unroll
            for (int rr = 0; rr < 2; rr++) {
                int r = wm * 32 + mf * 16 + (lane >> 2) + rr * 8;
                float bv = bias[r];
#pragma unroll
                for (int nf = 0; nf < 4; nf++)
#pragma unroll
                    for (int cp = 0; cp < 2; cp++) {
                        int c = wn * 32 + nf * 8 + (lane & 3) * 2 + cp;
                        float v = acc[mf][nf][rr * 2 + cp] + bv;
                        __nv_bfloat16 h_, l_;
                        split_bf16(v, h_, l_);
                        *(__nv_bfloat16*)(sm + SOFF + c * 272 + r * 2) = h_;
                        *(__nv_bfloat16*)(sm + SOFF + 17408 + c * 272 + r * 2) = l_;
                    }
            }
        __syncthreads();
#pragma unroll
        for (int l = 0; l < 8; l++) {
            int idx = t + 256 * l;             // 2048 uint4
            int row = idx >> 4, g = idx & 15;
            int hl = row >> 6, c = row & 63;
            uint4 v = *(const uint4*)(sm + SOFF + hl * 17408 + c * 272 + g * 16);
            *(uint4*)((hl ? g_vll : g_vlh) + (b * DIM + c0 + c) * RLOW + g * 8) = v;
        }
    }
}

// ================= attention: q plain bf16, 2-term phase-1 (R6-proven) =================
#define AQ_H 0
#define AK_H 5120
#define AK_L 15360
#define AV_H 25600
#define AV_L 34304
#define ATT_SMEM 43008
__global__ __launch_bounds__(128) void attn_mma()
{
    extern __shared__ char sm[];
    uint32_t sb = smem_u32(sm);
    const int t = threadIdx.x, lane = t & 31, w = t >> 5;
    const int n0 = blockIdx.x * 64, hh = blockIdx.y, b = blockIdx.z;

    {
        const __nv_bfloat16* qh = g_qh + ((b * HEADS + hh) * NSEQ + n0) * HD;
#pragma unroll
        for (int l = 0; l < 2; l++) {
            int idx = t + 128 * l;
            int row = idx >> 2, cg = idx & 3;
            *(uint4*)(sm + AQ_H + row * 80 + cg * 16) = *(const uint4*)(qh + row * HD + cg * 8);
        }
        const __nv_bfloat16* kh = g_klh + b * RLOW * DIM + hh * HD;
        const __nv_bfloat16* kl = g_kll + b * RLOW * DIM + hh * HD;
#pragma unroll
        for (int l = 0; l < 4; l++) {
            int idx = t + 128 * l;
            int row = idx >> 2, cg = idx & 3;
            *(uint4*)(sm + AK_H + row * 80 + cg * 16) = *(const uint4*)(kh + row * DIM + cg * 8);
            *(uint4*)(sm + AK_L + row * 80 + cg * 16) = *(const uint4*)(kl + row * DIM + cg * 8);
        }
        const __nv_bfloat16* vh = g_vlh + (b * DIM + hh * HD) * RLOW;
        const __nv_bfloat16* vl = g_vll + (b * DIM + hh * HD) * RLOW;
#pragma unroll
        for (int l = 0; l < 4; l++) {
            int idx = t + 128 * l;
            int row = idx >> 4, cg = idx & 15;
            *(uint4*)(sm + AV_H + row * 272 + cg * 16) = *(const uint4*)(vh + row * RLOW + cg * 8);
            *(uint4*)(sm + AV_L + row * 272 + cg * 16) = *(const uint4*)(vl + row * RLOW + cg * 8);
        }
    }
    __syncthreads();

    float acc[16][4] = {};
    {
        uint32_t qa = sb + AQ_H + (w * 16 + (lane & 15)) * 80 + ((lane >> 4) & 1) * 16;
        uint32_t ba = sb + AK_H + ((lane & 7) + ((lane >> 4) & 1) * 8) * 80 + ((lane >> 3) & 1) * 16;
#pragma unroll
        for (int ks = 0; ks < 2; ks++) {
            uint32_t aH[4];
            ldsm4(aH, qa + ks * 32);
#pragma unroll
            for (int np = 0; np < 8; np++) {
                uint32_t bh[4], bl[4];
                ldsm4(bh, ba + np * 1280 + ks * 32);
                ldsm4(bl, ba + (AK_L - AK_H) + np * 1280 + ks * 32);
                mma16816(acc[2 * np], aH, bh[0], bh[1]);
                mma16816(acc[2 * np], aH, bl[0], bl[1]);
                mma16816(acc[2 * np + 1], aH, bh[2], bh[3]);
                mma16816(acc[2 * np + 1], aH, bl[2], bl[3]);
            }
        }
    }

    float m0 = -1e30f, m1 = -1e30f;
#pragma unroll
    for (int i = 0; i < 16; i++) {
        m0 = fmaxf(m0, fmaxf(acc[i][0], acc[i][1]));
        m1 = fmaxf(m1, fmaxf(acc[i][2], acc[i][3]));
    }
    m0 = fmaxf(m0, __shfl_xor_sync(0xffffffff, m0, 1));
    m0 = fmaxf(m0, __shfl_xor_sync(0xffffffff, m0, 2));
    m1 = fmaxf(m1, __shfl_xor_sync(0xffffffff, m1, 1));
    m1 = fmaxf(m1, __shfl_xor_sync(0xffffffff, m1, 2));
    float s0 = 0.f, s1 = 0.f;
#pragma unroll
    for (int i = 0; i < 16; i++) {
        acc[i][0] = __expf(acc[i][0] - m0); s0 += acc[i][0];
        acc[i][1] = __expf(acc[i][1] - m0); s0 += acc[i][1];
        acc[i][2] = __expf(acc[i][2] - m1); s1 += acc[i][2];
        acc[i][3] = __expf(acc[i][3] - m1); s1 += acc[i][3];
    }
    s0 += __shfl_xor_sync(0xffffffff, s0, 1);
    s0 += __shfl_xor_sync(0xffffffff, s0, 2);
    s1 += __shfl_xor_sync(0xffffffff, s1, 1);
    s1 += __shfl_xor_sync(0xffffffff, s1, 2);

    float oacc[4][4] = {};
    {
        uint32_t va = sb + AV_H + ((lane & 7) + ((lane >> 4) & 1) * 8) * 272 + ((lane >> 3) & 1) * 16;
#pragma unroll
        for (int kt = 0; kt < 8; kt++) {
            uint32_t ah[4], al[4];
            ah[0] = pack_split(acc[2 * kt][0],     acc[2 * kt][1],     al[0]);
            ah[1] = pack_split(acc[2 * kt][2],     acc[2 * kt][3],     al[1]);
            ah[2] = pack_split(acc[2 * kt + 1][0], acc[2 * kt + 1][1], al[2]);
            ah[3] = pack_split(acc[2 * kt + 1][2], acc[2 * kt + 1][3], al[3]);
#pragma unroll
            for (int np = 0; np < 2; np++) {
                uint32_t vh[4], vl[4];
                ldsm4(vh, va + np * 16 * 272 + kt * 32);
                ldsm4(vl, va + (AV_L - AV_H) + np * 16 * 272 + kt * 32);
                mma16816(oacc[2 * np], ah, vh[0], vh[1]);
                mma16816(oacc[2 * np], al, vh[0], vh[1]);
                mma16816(oacc[2 * np], ah, vl[0], vl[1]);
                mma16816(oacc[2 * np + 1], ah, vh[2], vh[3]);
                mma16816(oacc[2 * np + 1], al, vh[2], vh[3]);
                mma16816(oacc[2 * np + 1], ah, vl[2], vl[3]);
            }
        }
    }

    {
        float inv0 = 1.0f / s0, inv1 = 1.0f / s1;
        int gr = lane >> 2;
        int row0 = n0 + w * 16 + gr, row1 = row0 + 8;
        int cbase = hh * HD + (lane & 3) * 2;
#pragma unroll
        for (int nf = 0; nf < 4; nf++) {
            int col = cbase + nf * 8;
            __nv_bfloat16 h_, l_;
            float v;
            v = oacc[nf][0] * inv0; split_bf16(v, h_, l_);
            g_ah[(b * NSEQ + row0) * DIM + col] = h_;     g_al[(b * NSEQ + row0) * DIM + col] = l_;
            v = oacc[nf][1] * inv0; split_bf16(v, h_, l_);
            g_ah[(b * NSEQ + row0) * DIM + col + 1] = h_; g_al[(b * NSEQ + row0) * DIM + col + 1] = l_;
            v = oacc[nf][2] * inv1; split_bf16(v, h_, l_);
            g_ah[(b * NSEQ + row1) * DIM + col] = h_;     g_al[(b * NSEQ + row1) * DIM + col] = l_;
            v = oacc[nf][3] * inv1; split_bf16(v, h_, l_);
            g_ah[(b * NSEQ + row1) * DIM + col + 1] = h_; g_al[(b * NSEQ + row1) * DIM + col + 1] = l_;
        }
    }
}

// ================= proj: M=128 N=64 K=192 (6 chunks) =================
__global__ __launch_bounds__(256, 2) void proj_mma(const float* __restrict__ bias,
                                                   float* __restrict__ out)
{
    extern __shared__ char sm[];
    uint32_t sb = smem_u32(sm);
    const int t = threadIdx.x, lane = t & 31, wid = t >> 5;
    const int wm = wid & 3, wn = wid >> 2;
    const int m0 = blockIdx.x * 128, j0 = blockIdx.y * 64;

    auto issue = [&](int i) {
        uint32_t st = sb + SOFF + (i & 1) * STG;
        int k0 = i * 32;
#pragma unroll
        for (int l = 0; l < 2; l++) {
            int idx = t + 256 * l;
            int row = idx >> 2, cg = idx & 3;
            uint32_t so = row * ROWB + cg * 16;
            int gi = (m0 + row) * DIM + k0 + cg * 8;
            cpa16(st + so, g_ah + gi);
            cpa16(st + S_AL + so, g_al + gi);
        }
        {
            int row = t >> 2, cg = t & 3;
            uint32_t so = row * ROWB + cg * 16;
            int gi = (j0 + row) * DIM + k0 + cg * 8;
            cpa16(st + S_BH + so, g_wph + gi);
            cpa16(st + S_BL + so, g_wpl + gi);
        }
        CPA_COMMIT();
    };

    float acc[2][4][4] = {};
    issue(0);
    for (int i = 0; i < 6; i++) {
        if (i < 5) { issue(i + 1); CPA_WAIT1(); } else { CPA_WAIT0(); }
        __syncthreads();
        compute_chunk(sb + SOFF + (i & 1) * STG, wm, wn, lane, acc);
        __syncthreads();
    }

#pragma unroll
    for (int mf = 0; mf < 2; mf++)
#pragma unroll
        for (int rr = 0; rr < 2; rr++) {
            int ml = wm * 32 + mf * 16 + (lane >> 2) + rr * 8;
#pragma unroll
            for (int nf = 0; nf < 4; nf++)
#pragma unroll
                for (int cp = 0; cp < 2; cp++) {
                    int c = wn * 32 + nf * 8 + (lane & 3) * 2 + cp;
                    *(float*)(sm + SOFF + ml * 272 + c * 4) =
                        acc[mf][nf][rr * 2 + cp] + bias[j0 + c];
                }
        }
    __syncthreads();
#pragma unroll
    for (int l = 0; l < 8; l++) {
        int idx = t + 256 * l;
        int row = idx >> 4, g = idx & 15;
        uint4 v = *(const uint4*)(sm + SOFF + row * 272 + g * 16);
        *(uint4*)(out + (m0 + row) * DIM + j0 + g * 4) = v;
    }
}

// ================= host =================
extern "C" void kernel_launch(void* const* d_in, const int* in_sizes, int n_in,
                              void* d_out, int out_size)
{
    const float* x      = (const float*)d_in[0];
    const float* qkv_w  = (const float*)d_in[1];
    const float* qkv_b  = (const float*)d_in[2];
    const float* E_w    = (const float*)d_in[3];
    const float* E_b    = (const float*)d_in[4];
    const float* F_w    = (const float*)d_in[5];
    const float* F_b    = (const float*)d_in[6];
    const float* proj_w = (const float*)d_in[7];
    const float* proj_b = (const float*)d_in[8];
    float* out = (float*)d_out;

    cudaFuncSetAttribute(qkv_mma, cudaFuncAttributeMaxDynamicSharedMemorySize, SMEM_GEMM);
    cudaFuncSetAttribute(lowrank_mma, cudaFuncAttributeMaxDynamicSharedMemorySize, SMEM_GEMM);
    cudaFuncSetAttribute(proj_mma, cudaFuncAttributeMaxDynamicSharedMemorySize, SMEM_GEMM);
    cudaFuncSetAttribute(attn_mma, cudaFuncAttributeMaxDynamicSharedMemorySize, ATT_SMEM);

    split_all<<<(N4TOT + 255) / 256, 256>>>(x, qkv_w, E_w, F_w, proj_w);
    qkv_mma<<<dim3(MTOT / 128, 9), 256, SMEM_GEMM>>>(qkv_b);
    lowrank_mma<<<dim3(3, BATCH, 2), 256, SMEM_GEMM>>>(E_b, F_b);
    attn_mma<<<dim3(NSEQ / 64, HEADS, BATCH), 128, ATT_SMEM>>>();
    proj_mma<<<dim3(MTOT / 128, 3), 256, SMEM_GEMM>>>(proj_b, out);
}

// round 8
// speedup vs baseline: 1.1424x; 1.0536x over previous
#include <cuda_runtime.h>
#include <cuda_bf16.h>
#include <cstdint>
#include <math.h>

#define DIM   192
#define HEADS 6
#define HD    32
#define RLOW  128
#define NSEQ  3136
#define BATCH 32
#define MTOT  (BATCH * NSEQ)   // 100352

// ================= scratch (device globals) =================
__device__ __align__(256) __nv_bfloat16 g_xh[MTOT * DIM], g_xl[MTOT * DIM];
__device__ __align__(256) __nv_bfloat16 g_qh[MTOT * DIM];                       // q bf16, pre-scaled
__device__ __align__(256) __nv_bfloat16 g_kTh[MTOT * DIM], g_kTl[MTOT * DIM];
__device__ __align__(256) __nv_bfloat16 g_vTh[MTOT * DIM], g_vTl[MTOT * DIM];
__device__ __align__(256) __nv_bfloat16 g_ah[MTOT * DIM], g_al[MTOT * DIM];
__device__ __align__(256) __nv_bfloat16 g_klh[BATCH * RLOW * DIM], g_kll[BATCH * RLOW * DIM];
__device__ __align__(256) __nv_bfloat16 g_vlh[BATCH * DIM * RLOW];              // vlow^T hi only
__device__ __align__(256) __nv_bfloat16 g_wqh[3 * DIM * DIM], g_wql[3 * DIM * DIM];
__device__ __align__(256) __nv_bfloat16 g_wph[DIM * DIM], g_wpl[DIM * DIM];
__device__ __align__(256) __nv_bfloat16 g_Eh[RLOW * NSEQ], g_El[RLOW * NSEQ];
__device__ __align__(256) __nv_bfloat16 g_Fh[RLOW * NSEQ], g_Fl[RLOW * NSEQ];

// ================= helpers =================
__device__ __forceinline__ uint32_t smem_u32(const void* p) {
    uint32_t a;
    asm("{ .reg .u64 t; cvta.to.shared.u64 t, %1; cvt.u32.u64 %0, t; }" : "=r"(a) : "l"(p));
    return a;
}
__device__ __forceinline__ void ldsm4(uint32_t r[4], uint32_t a) {
    asm volatile("ldmatrix.sync.aligned.m8n8.x4.shared.b16 {%0,%1,%2,%3}, [%4];"
                 : "=r"(r[0]), "=r"(r[1]), "=r"(r[2]), "=r"(r[3]) : "r"(a));
}
__device__ __forceinline__ void mma16816(float* c, const uint32_t a[4], uint32_t b0, uint32_t b1) {
    asm volatile("mma.sync.aligned.m16n8k16.row.col.f32.bf16.bf16.f32 "
                 "{%0,%1,%2,%3},{%4,%5,%6,%7},{%8,%9},{%0,%1,%2,%3};"
                 : "+f"(c[0]), "+f"(c[1]), "+f"(c[2]), "+f"(c[3])
                 : "r"(a[0]), "r"(a[1]), "r"(a[2]), "r"(a[3]), "r"(b0), "r"(b1));
}
__device__ __forceinline__ void cpa16(uint32_t saddr, const void* g) {
    asm volatile("cp.async.ca.shared.global [%0], [%1], 16;" :: "r"(saddr), "l"(g));
}
#define CPA_COMMIT() asm volatile("cp.async.commit_group;" ::: "memory")
#define CPA_WAIT1()  asm volatile("cp.async.wait_group 1;" ::: "memory")
#define CPA_WAIT0()  asm volatile("cp.async.wait_group 0;" ::: "memory")

__device__ __forceinline__ void split_bf16(float v, __nv_bfloat16& h, __nv_bfloat16& l) {
    h = __float2bfloat16(v);
    l = __float2bfloat16(v - __bfloat162float(h));
}
__device__ __forceinline__ uint32_t pack_bf16x2(float e0, float e1) {
    __nv_bfloat162 h = __floats2bfloat162_rn(e0, e1);
    return *reinterpret_cast<uint32_t*>(&h);
}

// ================= GEMM smem layout: K-chunk 32, 2 stages (R5-proven) =================
#define ROWB   80
#define S_AL   10240
#define S_BH   20480
#define S_BL   25600
#define STG    30720
#define SOFF   512
#define SMEM_GEMM (SOFF + 2 * STG)   // 61952

__device__ __forceinline__ void compute_chunk(uint32_t st, int wm, int wn, int lane,
                                              float acc[2][4][4])
{
    uint32_t a0r = st + (wm * 32 + (lane & 15)) * ROWB + ((lane >> 4) & 1) * 16;
    uint32_t b0r = st + S_BH + (wn * 32 + (lane & 7) + ((lane >> 4) & 1) * 8) * ROWB
                   + ((lane >> 3) & 1) * 16;
#pragma unroll
    for (int ks = 0; ks < 2; ks++) {
        uint32_t ah[2][4], al[2][4], bhA[4], bhB[4], blA[4], blB[4];
        ldsm4(ah[0], a0r + ks * 32);
        ldsm4(ah[1], a0r + 16 * ROWB + ks * 32);
        ldsm4(al[0], a0r + S_AL + ks * 32);
        ldsm4(al[1], a0r + S_AL + 16 * ROWB + ks * 32);
        ldsm4(bhA, b0r + ks * 32);
        ldsm4(bhB, b0r + 16 * ROWB + ks * 32);
        ldsm4(blA, b0r + (S_BL - S_BH) + ks * 32);
        ldsm4(blB, b0r + (S_BL - S_BH) + 16 * ROWB + ks * 32);
        uint32_t bh[4][2] = {{bhA[0], bhA[1]}, {bhA[2], bhA[3]}, {bhB[0], bhB[1]}, {bhB[2], bhB[3]}};
        uint32_t bl[4][2] = {{blA[0], blA[1]}, {blA[2], blA[3]}, {blB[0], blB[1]}, {blB[2], blB[3]}};
#pragma unroll
        for (int mf = 0; mf < 2; mf++)
#pragma unroll
            for (int nf = 0; nf < 4; nf++) {
                mma16816(acc[mf][nf], ah[mf], bh[nf][0], bh[nf][1]);
                mma16816(acc[mf][nf], al[mf], bh[nf][0], bh[nf][1]);
                mma16816(acc[mf][nf], ah[mf], bl[nf][0], bl[nf][1]);
            }
    }
}

// ================= fused split conversion =================
#define N4X (MTOT * DIM / 4)
#define N4Q (3 * DIM * DIM / 4)
#define N4E (RLOW * NSEQ / 4)
#define N4P (DIM * DIM / 4)
#define N4TOT (N4X + N4Q + 2 * N4E + N4P)
__global__ void split_all(const float* __restrict__ x, const float* __restrict__ qw,
                          const float* __restrict__ Ew, const float* __restrict__ Fw,
                          const float* __restrict__ pw)
{
    int i = blockIdx.x * blockDim.x + threadIdx.x;
    if (i >= N4TOT) return;
    const float* src;
    __nv_bfloat16 *hi, *lo;
    int off;
    if (i < N4X)                       { src = x;  hi = g_xh;  lo = g_xl;  off = i; }
    else if (i < N4X + N4Q)            { src = qw; hi = g_wqh; lo = g_wql; off = i - N4X; }
    else if (i < N4X + N4Q + N4E)      { src = Ew; hi = g_Eh;  lo = g_El;  off = i - N4X - N4Q; }
    else if (i < N4X + N4Q + 2 * N4E)  { src = Fw; hi = g_Fh;  lo = g_Fl;  off = i - N4X - N4Q - N4E; }
    else                               { src = pw; hi = g_wph; lo = g_wpl; off = i - N4X - N4Q - 2 * N4E; }
    float4 v = reinterpret_cast<const float4*>(src)[off];
    __nv_bfloat162 h01 = __floats2bfloat162_rn(v.x, v.y);
    __nv_bfloat162 h23 = __floats2bfloat162_rn(v.z, v.w);
    float2 f01 = __bfloat1622float2(h01), f23 = __bfloat1622float2(h23);
    __nv_bfloat162 l01 = __floats2bfloat162_rn(v.x - f01.x, v.y - f01.y);
    __nv_bfloat162 l23 = __floats2bfloat162_rn(v.z - f23.x, v.w - f23.y);
    reinterpret_cast<__nv_bfloat162*>(hi)[2 * off]     = h01;
    reinterpret_cast<__nv_bfloat162*>(hi)[2 * off + 1] = h23;
    reinterpret_cast<__nv_bfloat162*>(lo)[2 * off]     = l01;
    reinterpret_cast<__nv_bfloat162*>(lo)[2 * off + 1] = l23;
}

// ================= QKV: M=128 N=64 K=192 (6 chunks) =================
__global__ __launch_bounds__(256, 2) void qkv_mma(const float* __restrict__ bias)
{
    extern __shared__ char sm[];
    uint32_t sb = smem_u32(sm);
    const int t = threadIdx.x, lane = t & 31, wid = t >> 5;
    const int wm = wid & 3, wn = wid >> 2;
    const int m0 = blockIdx.x * 128, j0 = blockIdx.y * 64;
    int* rowoff = (int*)sm;

    if (t < 128) {
        int m   = m0 + t;
        int bb  = m / NSEQ, n = m - bb * NSEQ;
        int r56 = n / 56, c56 = n - r56 * 56;
        int hb  = r56 / 7, hi_ = r56 - hb * 7;
        int wb  = c56 / 7, wi = c56 - wb * 7;
        rowoff[t] = ((bb * 64 + hb * 8 + wb) * 49 + hi_ * 7 + wi) * DIM;
    }
    __syncthreads();

    auto issue = [&](int i) {
        uint32_t st = sb + SOFF + (i & 1) * STG;
        int k0 = i * 32;
#pragma unroll
        for (int l = 0; l < 2; l++) {
            int idx = t + 256 * l;
            int row = idx >> 2, cg = idx & 3;
            uint32_t so = row * ROWB + cg * 16;
            int gi = rowoff[row] + k0 + cg * 8;
            cpa16(st + so, g_xh + gi);
            cpa16(st + S_AL + so, g_xl + gi);
        }
        {
            int row = t >> 2, cg = t & 3;
            uint32_t so = row * ROWB + cg * 16;
            int gi = (j0 + row) * DIM + k0 + cg * 8;
            cpa16(st + S_BH + so, g_wqh + gi);
            cpa16(st + S_BL + so, g_wql + gi);
        }
        CPA_COMMIT();
    };

    float acc[2][4][4] = {};
    issue(0);
    for (int i = 0; i < 6; i++) {
        if (i < 5) { issue(i + 1); CPA_WAIT1(); } else { CPA_WAIT0(); }
        __syncthreads();
        compute_chunk(sb + SOFF + (i & 1) * STG, wm, wn, lane, acc);
        __syncthreads();
    }

    const int seg = j0 / DIM;          // 0=q 1=k 2=v
    const int jb  = j0 - seg * DIM;
    const float scale = 0.17677669529663687f;

    if (seg == 0) {
        // q: stage hi only, [n][c] stride 144
#pragma unroll
        for (int mf = 0; mf < 2; mf++)
#pragma unroll
            for (int rr = 0; rr < 2; rr++) {
                int ml = wm * 32 + mf * 16 + (lane >> 2) + rr * 8;
#pragma unroll
                for (int nf = 0; nf < 4; nf++)
#pragma unroll
                    for (int cp = 0; cp < 2; cp++) {
                        int c = wn * 32 + nf * 8 + (lane & 3) * 2 + cp;
                        float v = (acc[mf][nf][rr * 2 + cp] + bias[j0 + c]) * scale;
                        *(__nv_bfloat16*)(sm + SOFF + ml * 144 + c * 2) = __float2bfloat16(v);
                    }
            }
        __syncthreads();
        const int h0 = jb >> 5;
        {
            int row = t >> 1, q = t & 1;      // 256 tasks of 64B
            int m = m0 + row, b = m / NSEQ, n = m - b * NSEQ;
            const uint4* src = (const uint4*)(sm + SOFF + row * 144 + q * 64);
            __nv_bfloat16* dst = g_qh + ((b * HEADS + h0 + q) * NSEQ + n) * HD;
#pragma unroll
            for (int u = 0; u < 4; u++) ((uint4*)dst)[u] = src[u];
        }
    } else {
        // k/v transposed: stage [c][n], stride 272
#pragma unroll
        for (int mf = 0; mf < 2; mf++)
#pragma unroll
            for (int rr = 0; rr < 2; rr++) {
                int ml = wm * 32 + mf * 16 + (lane >> 2) + rr * 8;
#pragma unroll
                for (int nf = 0; nf < 4; nf++)
#pragma unroll
                    for (int cp = 0; cp < 2; cp++) {
                        int c = wn * 32 + nf * 8 + (lane & 3) * 2 + cp;
                        float v = acc[mf][nf][rr * 2 + cp] + bias[j0 + c];
                        __nv_bfloat16 h_, l_;
                        split_bf16(v, h_, l_);
                        *(__nv_bfloat16*)(sm + SOFF + c * 272 + ml * 2) = h_;
                        *(__nv_bfloat16*)(sm + SOFF + 17408 + c * 272 + ml * 2) = l_;
                    }
            }
        __syncthreads();
        __nv_bfloat16* H = (seg == 1) ? g_kTh : g_vTh;
        __nv_bfloat16* L = (seg == 1) ? g_kTl : g_vTl;
#pragma unroll
        for (int l = 0; l < 8; l++) {
            int idx = t + 256 * l;             // 2048 uint4
            int row = idx >> 4, g = idx & 15;
            int hl = row >> 6, c = row & 63;
            int m = m0 + g * 8, b = m / NSEQ, n = m - b * NSEQ;
            uint4 v = *(const uint4*)(sm + SOFF + hl * 17408 + c * 272 + g * 16);
            *(uint4*)((hl ? L : H) + (b * DIM + jb + c) * NSEQ + n) = v;
        }
    }
}

// ================= low-rank: M=128 N=64 K=3136 (98 chunks) =================
__global__ __launch_bounds__(256, 2) void lowrank_mma(const float* __restrict__ Eb,
                                                      const float* __restrict__ Fb)
{
    extern __shared__ char sm[];
    uint32_t sb = smem_u32(sm);
    const int t = threadIdx.x, lane = t & 31, wid = t >> 5;
    const int wm = wid & 3, wn = wid >> 2;
    const int c0 = blockIdx.x * 64, b = blockIdx.y, which = blockIdx.z;

    const __nv_bfloat16* Ah = which ? g_Fh : g_Eh;
    const __nv_bfloat16* Al = which ? g_Fl : g_El;
    const __nv_bfloat16* Bh = which ? g_vTh : g_kTh;
    const __nv_bfloat16* Bl = which ? g_vTl : g_kTl;
    const float* bias = which ? Fb : Eb;

    auto issue = [&](int i) {
        uint32_t st = sb + SOFF + (i & 1) * STG;
        int k0 = i * 32;
#pragma unroll
        for (int l = 0; l < 2; l++) {
            int idx = t + 256 * l;
            int row = idx >> 2, cg = idx & 3;
            uint32_t so = row * ROWB + cg * 16;
            int gi = row * NSEQ + k0 + cg * 8;
            cpa16(st + so, Ah + gi);
            cpa16(st + S_AL + so, Al + gi);
        }
        {
            int row = t >> 2, cg = t & 3;
            uint32_t so = row * ROWB + cg * 16;
            int gi = (b * DIM + c0 + row) * NSEQ + k0 + cg * 8;
            cpa16(st + S_BH + so, Bh + gi);
            cpa16(st + S_BL + so, Bl + gi);
        }
        CPA_COMMIT();
    };

    float acc[2][4][4] = {};
    issue(0);
    for (int i = 0; i < 98; i++) {
        if (i < 97) { issue(i + 1); CPA_WAIT1(); } else { CPA_WAIT0(); }
        __syncthreads();
        compute_chunk(sb + SOFF + (i & 1) * STG, wm, wn, lane, acc);
        __syncthreads();
    }

    if (which == 0) {
#pragma unroll
        for (int mf = 0; mf < 2; mf++)
#pragma unroll
            for (int rr = 0; rr < 2; rr++) {
                int r = wm * 32 + mf * 16 + (lane >> 2) + rr * 8;
                float bv = bias[r];
#pragma unroll
                for (int nf = 0; nf < 4; nf++)
#pragma unroll
                    for (int cp = 0; cp < 2; cp++) {
                        int c = wn * 32 + nf * 8 + (lane & 3) * 2 + cp;
                        float v = acc[mf][nf][rr * 2 + cp] + bv;
                        __nv_bfloat16 h_, l_;
                        split_bf16(v, h_, l_);
                        *(__nv_bfloat16*)(sm + SOFF + r * 144 + c * 2) = h_;
                        *(__nv_bfloat16*)(sm + SOFF + 18432 + r * 144 + c * 2) = l_;
                    }
            }
        __syncthreads();
#pragma unroll
        for (int l = 0; l < 2; l++) {
            int idx = t + 256 * l;             // 512 tasks of 64B
            int hl = idx >> 8, rem = idx & 255;
            int r = rem >> 1, half = rem & 1;
            const uint4* src = (const uint4*)(sm + SOFF + hl * 18432 + r * 144 + half * 64);
            __nv_bfloat16* dst = (hl ? g_kll : g_klh) + (b * RLOW + r) * DIM + c0 + half * 32;
#pragma unroll
            for (int u = 0; u < 4; u++) ((uint4*)dst)[u] = src[u];
        }
    } else {
        // vlow^T hi only: stage [c][r], stride 272
#pragma unroll
        for (int mf = 0; mf < 2; mf++)
#pragma unroll
            for (int rr = 0; rr < 2; rr++) {
                int r = wm * 32 + mf * 16 + (lane >> 2) + rr * 8;
                float bv = bias[r];
#pragma unroll
                for (int nf = 0; nf < 4; nf++)
#pragma unroll
                    for (int cp = 0; cp < 2; cp++) {
                        int c = wn * 32 + nf * 8 + (lane & 3) * 2 + cp;
                        float v = acc[mf][nf][rr * 2 + cp] + bv;
                        *(__nv_bfloat16*)(sm + SOFF + c * 272 + r * 2) = __float2bfloat16(v);
                    }
            }
        __syncthreads();
#pragma unroll
        for (int l = 0; l < 4; l++) {
            int idx = t + 256 * l;             // 1024 uint4 (64 c x 16)
            int c = idx >> 4, g = idx & 15;
            uint4 v = *(const uint4*)(sm + SOFF + c * 272 + g * 16);
            *(uint4*)(g_vlh + (b * DIM + c0 + c) * RLOW + g * 8) = v;
        }
    }
}

// ================= attention: 2-term phase-1, 1-term phase-3 =================
#define AQ_H 0
#define AK_H 5120
#define AK_L 15360
#define AV_H 25600
#define ATT_SMEM 34304
__global__ __launch_bounds__(128) void attn_mma()
{
    extern __shared__ char sm[];
    uint32_t sb = smem_u32(sm);
    const int t = threadIdx.x, lane = t & 31, w = t >> 5;
    const int n0 = blockIdx.x * 64, hh = blockIdx.y, b = blockIdx.z;

    {
        const __nv_bfloat16* qh = g_qh + ((b * HEADS + hh) * NSEQ + n0) * HD;
#pragma unroll
        for (int l = 0; l < 2; l++) {
            int idx = t + 128 * l;
            int row = idx >> 2, cg = idx & 3;
            *(uint4*)(sm + AQ_H + row * 80 + cg * 16) = *(const uint4*)(qh + row * HD + cg * 8);
        }
        const __nv_bfloat16* kh = g_klh + b * RLOW * DIM + hh * HD;
        const __nv_bfloat16* kl = g_kll + b * RLOW * DIM + hh * HD;
#pragma unroll
        for (int l = 0; l < 4; l++) {
            int idx = t + 128 * l;
            int row = idx >> 2, cg = idx & 3;
            *(uint4*)(sm + AK_H + row * 80 + cg * 16) = *(const uint4*)(kh + row * DIM + cg * 8);
            *(uint4*)(sm + AK_L + row * 80 + cg * 16) = *(const uint4*)(kl + row * DIM + cg * 8);
        }
        const __nv_bfloat16* vh = g_vlh + (b * DIM + hh * HD) * RLOW;
#pragma unroll
        for (int l = 0; l < 4; l++) {
            int idx = t + 128 * l;
            int row = idx >> 4, cg = idx & 15;
            *(uint4*)(sm + AV_H + row * 272 + cg * 16) = *(const uint4*)(vh + row * RLOW + cg * 8);
        }
    }
    __syncthreads();

    // phase 1: logits = qh·(klow_hi + klow_lo)
    float acc[16][4] = {};
    {
        uint32_t qa = sb + AQ_H + (w * 16 + (lane & 15)) * 80 + ((lane >> 4) & 1) * 16;
        uint32_t ba = sb + AK_H + ((lane & 7) + ((lane >> 4) & 1) * 8) * 80 + ((lane >> 3) & 1) * 16;
#pragma unroll
        for (int ks = 0; ks < 2; ks++) {
            uint32_t aH[4];
            ldsm4(aH, qa + ks * 32);
#pragma unroll
            for (int np = 0; np < 8; np++) {
                uint32_t bh[4], bl[4];
                ldsm4(bh, ba + np * 1280 + ks * 32);
                ldsm4(bl, ba + (AK_L - AK_H) + np * 1280 + ks * 32);
                mma16816(acc[2 * np], aH, bh[0], bh[1]);
                mma16816(acc[2 * np], aH, bl[0], bl[1]);
                mma16816(acc[2 * np + 1], aH, bh[2], bh[3]);
                mma16816(acc[2 * np + 1], aH, bl[2], bl[3]);
            }
        }
    }

    float m0 = -1e30f, m1 = -1e30f;
#pragma unroll
    for (int i = 0; i < 16; i++) {
        m0 = fmaxf(m0, fmaxf(acc[i][0], acc[i][1]));
        m1 = fmaxf(m1, fmaxf(acc[i][2], acc[i][3]));
    }
    m0 = fmaxf(m0, __shfl_xor_sync(0xffffffff, m0, 1));
    m0 = fmaxf(m0, __shfl_xor_sync(0xffffffff, m0, 2));
    m1 = fmaxf(m1, __shfl_xor_sync(0xffffffff, m1, 1));
    m1 = fmaxf(m1, __shfl_xor_sync(0xffffffff, m1, 2));
    float s0 = 0.f, s1 = 0.f;
#pragma unroll
    for (int i = 0; i < 16; i++) {
        acc[i][0] = __expf(acc[i][0] - m0); s0 += acc[i][0];
        acc[i][1] = __expf(acc[i][1] - m0); s0 += acc[i][1];
        acc[i][2] = __expf(acc[i][2] - m1); s1 += acc[i][2];
        acc[i][3] = __expf(acc[i][3] - m1); s1 += acc[i][3];
    }
    s0 += __shfl_xor_sync(0xffffffff, s0, 1);
    s0 += __shfl_xor_sync(0xffffffff, s0, 2);
    s1 += __shfl_xor_sync(0xffffffff, s1, 1);
    s1 += __shfl_xor_sync(0xffffffff, s1, 2);

    // phase 3: out = a_hi @ v_hi (1-term)
    float oacc[4][4] = {};
    {
        uint32_t va = sb + AV_H + ((lane & 7) + ((lane >> 4) & 1) * 8) * 272 + ((lane >> 3) & 1) * 16;
#pragma unroll
        for (int kt = 0; kt < 8; kt++) {
            uint32_t ah[4];
            ah[0] = pack_bf16x2(acc[2 * kt][0],     acc[2 * kt][1]);
            ah[1] = pack_bf16x2(acc[2 * kt][2],     acc[2 * kt][3]);
            ah[2] = pack_bf16x2(acc[2 * kt + 1][0], acc[2 * kt + 1][1]);
            ah[3] = pack_bf16x2(acc[2 * kt + 1][2], acc[2 * kt + 1][3]);
#pragma unroll
            for (int np = 0; np < 2; np++) {
                uint32_t vh[4];
                ldsm4(vh, va + np * 16 * 272 + kt * 32);
                mma16816(oacc[2 * np], ah, vh[0], vh[1]);
                mma16816(oacc[2 * np + 1], ah, vh[2], vh[3]);
            }
        }
    }

    {
        float inv0 = 1.0f / s0, inv1 = 1.0f / s1;
        int gr = lane >> 2;
        int row0 = n0 + w * 16 + gr, row1 = row0 + 8;
        int cbase = hh * HD + (lane & 3) * 2;
#pragma unroll
        for (int nf = 0; nf < 4; nf++) {
            int col = cbase + nf * 8;
            __nv_bfloat16 h_, l_;
            float v;
            v = oacc[nf][0] * inv0; split_bf16(v, h_, l_);
            g_ah[(b * NSEQ + row0) * DIM + col] = h_;     g_al[(b * NSEQ + row0) * DIM + col] = l_;
            v = oacc[nf][1] * inv0; split_bf16(v, h_, l_);
            g_ah[(b * NSEQ + row0) * DIM + col + 1] = h_; g_al[(b * NSEQ + row0) * DIM + col + 1] = l_;
            v = oacc[nf][2] * inv1; split_bf16(v, h_, l_);
            g_ah[(b * NSEQ + row1) * DIM + col] = h_;     g_al[(b * NSEQ + row1) * DIM + col] = l_;
            v = oacc[nf][3] * inv1; split_bf16(v, h_, l_);
            g_ah[(b * NSEQ + row1) * DIM + col + 1] = h_; g_al[(b * NSEQ + row1) * DIM + col + 1] = l_;
        }
    }
}

// ================= proj: M=128 N=64 K=192 (6 chunks) =================
__global__ __launch_bounds__(256, 2) void proj_mma(const float* __restrict__ bias,
                                                   float* __restrict__ out)
{
    extern __shared__ char sm[];
    uint32_t sb = smem_u32(sm);
    const int t = threadIdx.x, lane = t & 31, wid = t >> 5;
    const int wm = wid & 3, wn = wid >> 2;
    const int m0 = blockIdx.x * 128, j0 = blockIdx.y * 64;

    auto issue = [&](int i) {
        uint32_t st = sb + SOFF + (i & 1) * STG;
        int k0 = i * 32;
#pragma unroll
        for (int l = 0; l < 2; l++) {
            int idx = t + 256 * l;
            int row = idx >> 2, cg = idx & 3;
            uint32_t so = row * ROWB + cg * 16;
            int gi = (m0 + row) * DIM + k0 + cg * 8;
            cpa16(st + so, g_ah + gi);
            cpa16(st + S_AL + so, g_al + gi);
        }
        {
            int row = t >> 2, cg = t & 3;
            uint32_t so = row * ROWB + cg * 16;
            int gi = (j0 + row) * DIM + k0 + cg * 8;
            cpa16(st + S_BH + so, g_wph + gi);
            cpa16(st + S_BL + so, g_wpl + gi);
        }
        CPA_COMMIT();
    };

    float acc[2][4][4] = {};
    issue(0);
    for (int i = 0; i < 6; i++) {
        if (i < 5) { issue(i + 1); CPA_WAIT1(); } else { CPA_WAIT0(); }
        __syncthreads();
        compute_chunk(sb + SOFF + (i & 1) * STG, wm, wn, lane, acc);
        __syncthreads();
    }

#pragma unroll
    for (int mf = 0; mf < 2; mf++)
#pragma unroll
        for (int rr = 0; rr < 2; rr++) {
            int ml = wm * 32 + mf * 16 + (lane >> 2) + rr * 8;
#pragma unroll
            for (int nf = 0; nf < 4; nf++)
#pragma unroll
                for (int cp = 0; cp < 2; cp++) {
                    int c = wn * 32 + nf * 8 + (lane & 3) * 2 + cp;
                    *(float*)(sm + SOFF + ml * 272 + c * 4) =
                        acc[mf][nf][rr * 2 + cp] + bias[j0 + c];
                }
        }
    __syncthreads();
#pragma unroll
    for (int l = 0; l < 8; l++) {
        int idx = t + 256 * l;
        int row = idx >> 4, g = idx & 15;
        uint4 v = *(const uint4*)(sm + SOFF + row * 272 + g * 16);
        *(uint4*)(out + (m0 + row) * DIM + j0 + g * 4) = v;
    }
}

// ================= host =================
extern "C" void kernel_launch(void* const* d_in, const int* in_sizes, int n_in,
                              void* d_out, int out_size)
{
    const float* x      = (const float*)d_in[0];
    const float* qkv_w  = (const float*)d_in[1];
    const float* qkv_b  = (const float*)d_in[2];
    const float* E_w    = (const float*)d_in[3];
    const float* E_b    = (const float*)d_in[4];
    const float* F_w    = (const float*)d_in[5];
    const float* F_b    = (const float*)d_in[6];
    const float* proj_w = (const float*)d_in[7];
    const float* proj_b = (const float*)d_in[8];
    float* out = (float*)d_out;

    cudaFuncSetAttribute(qkv_mma, cudaFuncAttributeMaxDynamicSharedMemorySize, SMEM_GEMM);
    cudaFuncSetAttribute(lowrank_mma, cudaFuncAttributeMaxDynamicSharedMemorySize, SMEM_GEMM);
    cudaFuncSetAttribute(proj_mma, cudaFuncAttributeMaxDynamicSharedMemorySize, SMEM_GEMM);
    cudaFuncSetAttribute(attn_mma, cudaFuncAttributeMaxDynamicSharedMemorySize, ATT_SMEM);

    split_all<<<(N4TOT + 255) / 256, 256>>>(x, qkv_w, E_w, F_w, proj_w);
    qkv_mma<<<dim3(MTOT / 128, 9), 256, SMEM_GEMM>>>(qkv_b);
    lowrank_mma<<<dim3(3, BATCH, 2), 256, SMEM_GEMM>>>(E_b, F_b);
    attn_mma<<<dim3(NSEQ / 64, HEADS, BATCH), 128, ATT_SMEM>>>();
    proj_mma<<<dim3(MTOT / 128, 3), 256, SMEM_GEMM>>>(proj_b, out);
}